// round 8
// baseline (speedup 1.0000x reference)
#include <cuda_runtime.h>
#include <cuda_bf16.h>
#include <stdint.h>

// ============================================================================
// LightAttention via mma.sync m16n8k8 TF32 (RNE-rounded fp32 operands).
// 128x128 CTA tiles, 2 CTAs/SM.
//   proj_all: 0: eQ=exp((xq@Wq+b)*s) (+col sums)  1: eKT=exp(...)^T (+row sums)
//             2: VT=(xv@Wv+b)^T            [2-stage: conv x + async W]
//   combine_sums; bm_split (split-K x2, ONE wave, 3-stage); bm_combine;
//   z_gemm (3-stage): Z = eQ @ BmT^T.
// Softmax max dropped (exp args in [-0.75,0.75]; max cancels algebraically).
// ============================================================================

#define B_SZ   8
#define N_SEQ  4096
#define DM     512
#define M_ALL  (B_SZ * N_SEQ)
#define ELTS   ((size_t)M_ALL * DM)

static __device__ __constant__ float kINVS = 0.21022410381342863f; // 512^-0.25

// ---------------- scratch ----------------
__device__ __align__(16) float g_Wt[3 * DM * DM];
__device__ __align__(16) float g_eQ[ELTS];
__device__ __align__(16) float g_eKT[ELTS];
__device__ __align__(16) float g_VT[ELTS];
__device__ __align__(16) float g_BmT[B_SZ * DM * DM];
__device__ __align__(16) float g_BmP[2 * B_SZ * DM * DM];
__device__ float g_pq[256 * DM];
__device__ float g_pk[256 * DM];
__device__ float g_sum[2 * B_SZ * DM];

// ---------------- helpers ----------------
__device__ __forceinline__ uint32_t smem_u32(const void* p) {
    uint32_t r;
    asm("{ .reg .u64 t; cvta.to.shared.u64 t, %1; cvt.u32.u64 %0, t; }" : "=r"(r) : "l"(p));
    return r;
}
// RNE round fp32 -> tf32
__device__ __forceinline__ float rtf(float x) {
    uint32_t u = __float_as_uint(x);
    u = (u + 0x00000FFFu + ((u >> 13) & 1u)) & 0xFFFFE000u;
    return __uint_as_float(u);
}
__device__ __forceinline__ void ldmx4(uint32_t r[4], uint32_t addr) {
    asm volatile("ldmatrix.sync.aligned.m8n8.x4.shared.b16 {%0,%1,%2,%3}, [%4];"
                 : "=r"(r[0]), "=r"(r[1]), "=r"(r[2]), "=r"(r[3]) : "r"(addr));
}
__device__ __forceinline__ void mmatf32(float c[4], const uint32_t a[4],
                                        uint32_t b0, uint32_t b1) {
    asm volatile("mma.sync.aligned.m16n8k8.row.col.f32.tf32.tf32.f32 "
                 "{%0,%1,%2,%3}, {%4,%5,%6,%7}, {%8,%9}, {%0,%1,%2,%3};"
                 : "+f"(c[0]), "+f"(c[1]), "+f"(c[2]), "+f"(c[3])
                 : "r"(a[0]), "r"(a[1]), "r"(a[2]), "r"(a[3]), "r"(b0), "r"(b1));
}

#define PITCH    144            // 32 fp32 (128B) + 16B pad
#define MATB     18432          // 128 * 144
#define STAGE_B  36864          // 2 matrices
#define SMEM_PROJ 73728         // 2 stages (proj)
#define SMEM_GEMM 110592        // 3 stages (bm / z)
#define SPB2     528
#define SW_OFF   67584

// k32 chunk: A[128,32] @ B[128,32]^T, warp 64x32.
__device__ __forceinline__ void gemm_tf32(uint32_t aBase, uint32_t bBase,
                                          int wm, int wn, int lane, float acc[4][4][4]) {
    const int arow = wm * 64 + (lane & 15);
    const int brow = wn * 32 + (lane & 15);
    const uint32_t lhi = (uint32_t)((lane >> 4) * 16);
#pragma unroll
    for (int s8 = 0; s8 < 4; ++s8) {
        const uint32_t kb = (uint32_t)(s8 * 32) + lhi;
        uint32_t a[4][4], b[2][4];
#pragma unroll
        for (int mt = 0; mt < 4; ++mt)
            ldmx4(a[mt], aBase + (uint32_t)(arow + mt * 16) * PITCH + kb);
#pragma unroll
        for (int ng = 0; ng < 2; ++ng)
            ldmx4(b[ng], bBase + (uint32_t)(brow + ng * 16) * PITCH + kb);
#pragma unroll
        for (int mt = 0; mt < 4; ++mt)
#pragma unroll
            for (int nt = 0; nt < 4; ++nt)
                mmatf32(acc[mt][nt], a[mt], b[nt >> 1][nt & 1], b[nt >> 1][(nt & 1) + 2]);
    }
}

// ---------------- unified projection (2-stage, conv x + async W) ----------------
__global__ __launch_bounds__(256, 2)
void proj_all_kernel(const float* __restrict__ xq, const float* __restrict__ xk,
                     const float* __restrict__ xv,
                     const float* __restrict__ bq, const float* __restrict__ bk,
                     const float* __restrict__ bvv) {
    extern __shared__ char smx[];
    const uint32_t smbase = smem_u32(smx);
    const int tid = threadIdx.x, wid = tid >> 5, lane = tid & 31;
    const int wm = wid & 1, wn = wid >> 1;
    const int bx = blockIdx.x, byr = blockIdx.y, mz = blockIdx.z;
    const bool isQ = (mz == 0);

    const float* X; const float* bias;
    if (mz == 0)      { X = xq; bias = bq;  }
    else if (mz == 1) { X = xk; bias = bk;  }
    else              { X = xv; bias = bvv; }
    const float* Wp = g_Wt + (size_t)mz * DM * DM;

    int b = 0, ntile = 0, dtile = 0;
    size_t xRow0, wRow0;
    if (isQ) { xRow0 = (size_t)byr * 128; wRow0 = (size_t)bx * 128; }
    else {
        b = byr >> 5; ntile = byr & 31; dtile = bx;
        xRow0 = (size_t)b * 4096 + (size_t)ntile * 128;
        wRow0 = (size_t)dtile * 128;
    }
    const float* xP = X + xRow0 * 512;
    const float* wP = Wp + wRow0 * 512;
    const uint32_t convOff = isQ ? 0u : (uint32_t)MATB;
    const uint32_t asyOff  = isQ ? (uint32_t)MATB : 0u;

    float4 cr[4];
    auto ldgConv = [&](int kc) {
#pragma unroll
        for (int j = 0; j < 4; ++j) {
            const int lin = tid + j * 256, row = lin >> 3, kq = lin & 7;
            cr[j] = *reinterpret_cast<const float4*>(xP + (size_t)row * 512 + kc + kq * 4);
        }
    };
    auto stsConv = [&](int s) {
        char* bp = smx + s * STAGE_B + convOff;
#pragma unroll
        for (int j = 0; j < 4; ++j) {
            const int lin = tid + j * 256, row = lin >> 3, kq = lin & 7;
            float4 v;
            v.x = rtf(cr[j].x); v.y = rtf(cr[j].y);
            v.z = rtf(cr[j].z); v.w = rtf(cr[j].w);
            *reinterpret_cast<float4*>(bp + row * PITCH + kq * 16) = v;
        }
    };
    auto asyncLoad = [&](int s, int kc) {
        const uint32_t d0 = smbase + s * STAGE_B + asyOff;
#pragma unroll
        for (int i = 0; i < 4; ++i) {
            const int idx = tid + i * 256, row = idx >> 3, c16 = idx & 7;
            const uint32_t d = d0 + row * PITCH + c16 * 16;
            const float* g = wP + (size_t)row * 512 + kc + c16 * 4;
            asm volatile("cp.async.cg.shared.global [%0], [%1], 16;" :: "r"(d), "l"(g));
        }
        asm volatile("cp.async.commit_group;");
    };

    float acc[4][4][4];
#pragma unroll
    for (int a = 0; a < 4; ++a)
#pragma unroll
        for (int b2 = 0; b2 < 4; ++b2)
#pragma unroll
            for (int c = 0; c < 4; ++c) acc[a][b2][c] = 0.f;

    ldgConv(0);
    stsConv(0);
    asyncLoad(0, 0);
    ldgConv(32);

    for (int c = 0; c < 16; ++c) {
        const int s = c & 1;
        asm volatile("cp.async.wait_group 0;" ::: "memory");
        __syncthreads();
        if (c + 1 < 16) { asyncLoad(1 - s, (c + 1) * 32); stsConv(1 - s); }
        if (c + 2 < 16) ldgConv((c + 2) * 32);
        gemm_tf32(smbase + s * STAGE_B, smbase + s * STAGE_B + MATB, wm, wn, lane, acc);
    }
    __syncthreads();

    // ---------------- fused epilogue ----------------
    const int r0 = wm * 64 + (lane >> 2);
    const int c0 = wn * 32 + (lane & 3) * 2;

    float bcol[4][2], brow[4][2];
    if (isQ) {
#pragma unroll
        for (int nt = 0; nt < 4; ++nt) {
            const int cc = bx * 128 + c0 + nt * 8;
            bcol[nt][0] = bias[cc]; bcol[nt][1] = bias[cc + 1];
        }
    } else {
#pragma unroll
        for (int mt = 0; mt < 4; ++mt)
#pragma unroll
            for (int p = 0; p < 2; ++p)
                brow[mt][p] = bias[dtile * 128 + r0 + mt * 16 + p * 8];
    }

    float ps[4][2];
#pragma unroll
    for (int a = 0; a < 4; ++a) { ps[a][0] = 0.f; ps[a][1] = 0.f; }

    char* st = smx;
#pragma unroll
    for (int mt = 0; mt < 4; ++mt)
#pragma unroll
        for (int nt = 0; nt < 4; ++nt)
#pragma unroll
            for (int p = 0; p < 2; ++p) {
                float v0 = acc[mt][nt][p * 2], v1 = acc[mt][nt][p * 2 + 1];
                if (isQ) { v0 += bcol[nt][0]; v1 += bcol[nt][1]; }
                else     { v0 += brow[mt][p]; v1 += brow[mt][p]; }
                if (mz != 2) {
                    v0 = __expf(v0 * kINVS);
                    v1 = __expf(v1 * kINVS);
                }
                v0 = rtf(v0); v1 = rtf(v1);
                if (mz == 0) { ps[nt][0] += v0; ps[nt][1] += v1; }
                if (mz == 1) { ps[mt][p] += v0 + v1; }
                const int row = r0 + mt * 16 + p * 8;
                const int col = c0 + nt * 8;
                float2 o; o.x = v0; o.y = v1;
                *reinterpret_cast<float2*>(st + row * SPB2 + col * 4) = o;
            }

    float* sW = reinterpret_cast<float*>(smx + SW_OFF);
    if (mz == 0) {
#pragma unroll
        for (int nt = 0; nt < 4; ++nt)
#pragma unroll
            for (int j = 0; j < 2; ++j) {
                ps[nt][j] += __shfl_xor_sync(0xffffffffu, ps[nt][j], 4);
                ps[nt][j] += __shfl_xor_sync(0xffffffffu, ps[nt][j], 8);
                ps[nt][j] += __shfl_xor_sync(0xffffffffu, ps[nt][j], 16);
            }
        if ((lane >> 2) == 0) {
#pragma unroll
            for (int nt = 0; nt < 4; ++nt)
#pragma unroll
                for (int j = 0; j < 2; ++j)
                    sW[wm * 128 + wn * 32 + nt * 8 + (lane & 3) * 2 + j] = ps[nt][j];
        }
    } else if (mz == 1) {
#pragma unroll
        for (int mt = 0; mt < 4; ++mt)
#pragma unroll
            for (int p = 0; p < 2; ++p) {
                ps[mt][p] += __shfl_xor_sync(0xffffffffu, ps[mt][p], 1);
                ps[mt][p] += __shfl_xor_sync(0xffffffffu, ps[mt][p], 2);
            }
        if ((lane & 3) == 0) {
#pragma unroll
            for (int mt = 0; mt < 4; ++mt)
#pragma unroll
                for (int p = 0; p < 2; ++p)
                    sW[wn * 128 + wm * 64 + mt * 16 + p * 8 + (lane >> 2)] = ps[mt][p];
        }
    }
    __syncthreads();

    float* outP;
    size_t base, stride;
    if (isQ) {
        outP = g_eQ; stride = 512;
        base = (size_t)byr * 128 * 512 + bx * 128;
    } else {
        outP = (mz == 1) ? g_eKT : g_VT; stride = 4096;
        base = ((size_t)b * 512 + dtile * 128) * 4096 + (size_t)ntile * 128;
    }
#pragma unroll
    for (int it = 0; it < 16; ++it) {
        const int idx = tid + it * 256, row = idx >> 5, seg = idx & 31;
        const float4 v = *reinterpret_cast<const float4*>(st + row * SPB2 + seg * 16);
        *reinterpret_cast<float4*>(outP + base + (size_t)row * stride + seg * 4) = v;
    }
    if (mz == 0 && tid < 128)
        g_pq[(size_t)byr * 512 + bx * 128 + tid] = sW[tid] + sW[128 + tid];
    if (mz == 1 && tid < 128)
        g_pk[((size_t)b * 32 + ntile) * 512 + dtile * 128 + tid] =
            sW[tid] + sW[128 + tid] + sW[256 + tid] + sW[384 + tid];
}

// ---------------- combine sums ----------------
__global__ __launch_bounds__(512)
void combine_sums_kernel() {
    const int i = blockIdx.x * 512 + threadIdx.x;
    const int b = i >> 9, d = i & 511;
    float q = 0.f, k = 0.f;
#pragma unroll
    for (int j = 0; j < 32; ++j) {
        q += g_pq[(b * 32 + j) * 512 + d];
        k += g_pk[(b * 32 + j) * 512 + d];
    }
    g_sum[i] = q;
    g_sum[4096 + i] = k;
}

// ---------------- async stage loader (2 matrices) ----------------
__device__ __forceinline__ void load2(uint32_t smbase, int s,
                                      const float* aP, int as,
                                      const float* bP, int bs, int kc, int tid) {
    const uint32_t base = smbase + s * STAGE_B;
#pragma unroll
    for (int i = 0; i < 4; ++i) {
        const int idx = tid + i * 256, row = idx >> 3, c16 = idx & 7;
        const uint32_t d = base + row * PITCH + c16 * 16;
        const float* g = aP + (size_t)row * as + kc + c16 * 4;
        asm volatile("cp.async.cg.shared.global [%0], [%1], 16;" :: "r"(d), "l"(g));
    }
#pragma unroll
    for (int i = 0; i < 4; ++i) {
        const int idx = tid + i * 256, row = idx >> 3, c16 = idx & 7;
        const uint32_t d = base + MATB + row * PITCH + c16 * 16;
        const float* g = bP + (size_t)row * bs + kc + c16 * 4;
        asm volatile("cp.async.cg.shared.global [%0], [%1], 16;" :: "r"(d), "l"(g));
    }
    asm volatile("cp.async.commit_group;");
}

// 3-stage mainloop over nch chunks of K=32 starting at k0.
template<int NCH>
__device__ __forceinline__ void mainloop3(uint32_t smbase,
                                          const float* aP, int as,
                                          const float* bP, int bs, int k0,
                                          int tid, int wm, int wn, int lane,
                                          float acc[4][4][4]) {
    load2(smbase, 0, aP, as, bP, bs, k0, tid);
    load2(smbase, 1, aP, as, bP, bs, k0 + 32, tid);
#pragma unroll 1
    for (int c = 0; c < NCH; ++c) {
        const int s = c % 3;
        if (c + 1 < NCH) { asm volatile("cp.async.wait_group 1;" ::: "memory"); }
        else             { asm volatile("cp.async.wait_group 0;" ::: "memory"); }
        __syncthreads();
        if (c + 2 < NCH) load2(smbase, (c + 2) % 3, aP, as, bP, bs, k0 + (c + 2) * 32, tid);
        gemm_tf32(smbase + s * STAGE_B, smbase + s * STAGE_B + MATB, wm, wn, lane, acc);
    }
}

// ---------------- Bm split-K x2: grid (4, 8, 8) = 256 CTAs (ONE wave) --------
__global__ __launch_bounds__(256, 2)
void bm_split_kernel() {
    extern __shared__ char smx[];
    const uint32_t smbase = smem_u32(smx);
    const int tid = threadIdx.x, wid = tid >> 5, lane = tid & 31;
    const int wm = wid & 1, wn = wid >> 1;
    const int bx = blockIdx.x, bz = blockIdx.z;
    const int split = blockIdx.y >> 2, ey = blockIdx.y & 3;
    const int k0 = split * 2048;

    const float* aP = g_VT + ((size_t)bz * 512 + ey * 128) * 4096;
    const float* bP = g_eKT + ((size_t)bz * 512 + bx * 128) * 4096;

    float acc[4][4][4];
#pragma unroll
    for (int a = 0; a < 4; ++a)
#pragma unroll
        for (int b2 = 0; b2 < 4; ++b2)
#pragma unroll
            for (int c = 0; c < 4; ++c) acc[a][b2][c] = 0.f;

    mainloop3<64>(smbase, aP, 4096, bP, 4096, k0, tid, wm, wn, lane, acc);

    const int r0 = wm * 64 + (lane >> 2);
    const int c0 = wn * 32 + (lane & 3) * 2;
    float* outP = g_BmP + ((size_t)split * 8 + bz) * DM * DM;
#pragma unroll
    for (int mt = 0; mt < 4; ++mt)
#pragma unroll
        for (int nt = 0; nt < 4; ++nt)
#pragma unroll
            for (int p = 0; p < 2; ++p) {
                const int e = ey * 128 + r0 + mt * 16 + p * 8;
                const int d = bx * 128 + c0 + nt * 8;
                float2 o;
                o.x = acc[mt][nt][p * 2];
                o.y = acc[mt][nt][p * 2 + 1];
                *reinterpret_cast<float2*>(outP + (size_t)e * DM + d) = o;
            }
}

// ---------------- Bm combine ----------------
__global__ __launch_bounds__(256)
void bm_combine_kernel() {
    const size_t idx = (size_t)blockIdx.x * 256 + threadIdx.x;
    const size_t e4 = idx * 4;
    const int bz = (int)(e4 >> 18);
    const int d0 = (int)(e4 & 511);
    float4 s = reinterpret_cast<const float4*>(g_BmP)[idx];
    const float4 t = reinterpret_cast<const float4*>(g_BmP + (size_t)8 * DM * DM)[idx];
    s.x += t.x; s.y += t.y; s.z += t.z; s.w += t.w;
    const float* sq = g_sum + bz * 512 + d0;
    const float* sk = g_sum + 4096 + bz * 512 + d0;
    s.x = rtf(s.x / (sk[0] * sq[0]));
    s.y = rtf(s.y / (sk[1] * sq[1]));
    s.z = rtf(s.z / (sk[2] * sq[2]));
    s.w = rtf(s.w / (sk[3] * sq[3]));
    reinterpret_cast<float4*>(g_BmT)[idx] = s;
}

// ---------------- Z GEMM (3-stage): grid (4, 32, 8) ----------------
__global__ __launch_bounds__(256, 2)
void z_gemm_kernel(float* __restrict__ Z) {
    extern __shared__ char smx[];
    const uint32_t smbase = smem_u32(smx);
    const int tid = threadIdx.x, wid = tid >> 5, lane = tid & 31;
    const int wm = wid & 1, wn = wid >> 1;
    const int bx = blockIdx.x, by = blockIdx.y, bz = blockIdx.z;

    const float* aP = g_eQ + ((size_t)bz * 4096 + by * 128) * 512;
    const float* bP = g_BmT + ((size_t)bz * 512 + bx * 128) * 512;

    float acc[4][4][4];
#pragma unroll
    for (int a = 0; a < 4; ++a)
#pragma unroll
        for (int b2 = 0; b2 < 4; ++b2)
#pragma unroll
            for (int c = 0; c < 4; ++c) acc[a][b2][c] = 0.f;

    mainloop3<16>(smbase, aP, 512, bP, 512, 0, tid, wm, wn, lane, acc);

    const int r0 = wm * 64 + (lane >> 2);
    const int c0 = wn * 32 + (lane & 3) * 2;
#pragma unroll
    for (int mt = 0; mt < 4; ++mt)
#pragma unroll
        for (int nt = 0; nt < 4; ++nt)
#pragma unroll
            for (int p = 0; p < 2; ++p) {
                const int cc = bx * 128 + c0 + nt * 8;
                const size_t row = (size_t)bz * 4096 + by * 128 + r0 + mt * 16 + p * 8;
                float2 o;
                o.x = acc[mt][nt][p * 2];
                o.y = acc[mt][nt][p * 2 + 1];
                *reinterpret_cast<float2*>(Z + row * 512 + cc) = o;
            }
}

// ---------------- weight transpose + tf32 round ----------------
__global__ __launch_bounds__(256)
void wt_round_kernel(const float* __restrict__ w0, const float* __restrict__ w1,
                     const float* __restrict__ w2) {
    __shared__ float t[32][33];
    const int mz = blockIdx.z;
    const float* src = (mz == 0) ? w0 : (mz == 1) ? w1 : w2;
    float* dst = g_Wt + (size_t)mz * DM * DM;
    const int c0 = blockIdx.x * 32, r0 = blockIdx.y * 32;
#pragma unroll
    for (int i = 0; i < 4; ++i) {
        const int r = r0 + threadIdx.y + i * 8;
        t[threadIdx.y + i * 8][threadIdx.x] = src[(size_t)r * DM + c0 + threadIdx.x];
    }
    __syncthreads();
#pragma unroll
    for (int i = 0; i < 4; ++i) {
        const int c = c0 + threadIdx.y + i * 8;
        const int r = r0 + threadIdx.x;
        dst[(size_t)c * DM + r] = rtf(t[threadIdx.x][threadIdx.y + i * 8]);
    }
}

// ---------------- launch ----------------
extern "C" void kernel_launch(void* const* d_in, const int* in_sizes, int n_in,
                              void* d_out, int out_size) {
    const float* x_q = (const float*)d_in[0];
    const float* x_k = (const float*)d_in[1];
    const float* x_v = (const float*)d_in[2];
    const float* W_q = (const float*)d_in[3];
    const float* b_q = (const float*)d_in[4];
    const float* W_k = (const float*)d_in[5];
    const float* b_k = (const float*)d_in[6];
    const float* W_v = (const float*)d_in[7];
    const float* b_v = (const float*)d_in[8];
    float* Z = (float*)d_out;

    cudaFuncSetAttribute(proj_all_kernel, cudaFuncAttributeMaxDynamicSharedMemorySize, SMEM_PROJ);
    cudaFuncSetAttribute(bm_split_kernel, cudaFuncAttributeMaxDynamicSharedMemorySize, SMEM_GEMM);
    cudaFuncSetAttribute(z_gemm_kernel, cudaFuncAttributeMaxDynamicSharedMemorySize, SMEM_GEMM);

    wt_round_kernel<<<dim3(16, 16, 3), dim3(32, 8)>>>(W_q, W_k, W_v);

    proj_all_kernel<<<dim3(4, 256, 3), 256, SMEM_PROJ>>>(
        x_q, x_k, x_v, b_q, b_k, b_v);

    combine_sums_kernel<<<8, 512>>>();

    bm_split_kernel<<<dim3(4, 8, 8), 256, SMEM_GEMM>>>();
    bm_combine_kernel<<<2048, 256>>>();

    z_gemm_kernel<<<dim3(4, 32, 8), 256, SMEM_GEMM>>>(Z);
}